// round 15
// baseline (speedup 1.0000x reference)
#include <cuda_runtime.h>
#include <cuda_bf16.h>

#define NN    64
#define CC    128
#define HWP   3136
#define MTOT  200704
#define EPSI  1e-5f
#define TITER 10
#define NSB   128
#define GCHUNK 784
#define GBLK  256

// gram smem: [buf 0/1][128 rows][48B] (hi only, 1-pass)
#define PITCHB 48
#define GBUF   (128 * PITCHB)

// whit smem: wm [c=128][d, pitch 132 fl] tf32 ; X [p=64][d, pitch 132 fl] tf32
#define WP 132
#define XP2 132
#define S_X    (128 * WP * 4)
#define S_BIAS (S_X + 64 * XP2 * 4)
#define WHIT_SMEM (S_BIAS + 512)

// ---------------- scratch ----------------
__device__ float d_gpart[GBLK * CC * CC];
__device__ float d_cpart[GBLK * CC];
__device__ float d_gram[CC * CC];
__device__ float d_chsum[CC];
__device__ float d_Sig[CC * CC];
__device__ float d_P2[2][CC * CC];
__device__ float d_wmf[CC * CC];
__device__ float d_bias2[CC];
__device__ float d_trace;
__device__ unsigned g_bar;

// ---------------- helpers ----------------
__device__ __forceinline__ unsigned smem_u32(const void* p) {
    unsigned r; asm("{ .reg .u64 t; cvta.to.shared.u64 t, %1; cvt.u32.u64 %0, t; }" : "=r"(r) : "l"(p)); return r;
}
__device__ __forceinline__ void ldsm_x4(unsigned &r0, unsigned &r1, unsigned &r2, unsigned &r3, unsigned a) {
    asm volatile("ldmatrix.sync.aligned.m8n8.x4.shared.b16 {%0,%1,%2,%3}, [%4];"
                 : "=r"(r0), "=r"(r1), "=r"(r2), "=r"(r3) : "r"(a));
}
__device__ __forceinline__ void mma_bf16(float* d, unsigned a0, unsigned a1, unsigned a2, unsigned a3,
                                         unsigned b0, unsigned b1) {
    asm volatile("mma.sync.aligned.m16n8k16.row.col.f32.bf16.bf16.f32 "
                 "{%0,%1,%2,%3}, {%4,%5,%6,%7}, {%8,%9}, {%0,%1,%2,%3};"
                 : "+f"(d[0]), "+f"(d[1]), "+f"(d[2]), "+f"(d[3])
                 : "r"(a0), "r"(a1), "r"(a2), "r"(a3), "r"(b0), "r"(b1));
}
__device__ __forceinline__ void mma_tf32(float* d, unsigned a0, unsigned a1, unsigned a2, unsigned a3,
                                         unsigned b0, unsigned b1) {
    asm volatile("mma.sync.aligned.m16n8k8.row.col.f32.tf32.tf32.f32 "
                 "{%0,%1,%2,%3}, {%4,%5,%6,%7}, {%8,%9}, {%0,%1,%2,%3};"
                 : "+f"(d[0]), "+f"(d[1]), "+f"(d[2]), "+f"(d[3])
                 : "r"(a0), "r"(a1), "r"(a2), "r"(a3), "r"(b0), "r"(b1));
}
__device__ __forceinline__ unsigned pkbf(float a, float b) {
    __nv_bfloat162 t(__float2bfloat16(a), __float2bfloat16(b));
    return *(unsigned*)&t;
}
__device__ __forceinline__ unsigned cvt_tf32(float f) {
    unsigned r; asm("cvt.rna.tf32.f32 %0, %1;" : "=r"(r) : "f"(f)); return r;
}

// ---------------- kernel 1: Gram, 1-pass bf16 + prefetch-2 ----------------
__global__ void __launch_bounds__(256, 2) gram_kernel(const float* __restrict__ X) {
    __shared__ __align__(16) char sm[2 * GBUF];
    __shared__ float chs[CC];
    const int tid = threadIdx.x, wid = tid >> 5, lane = tid & 31;
    const unsigned smb = smem_u32(sm);
    const int n = blockIdx.x >> 2;
    const int pbase = (blockIdx.x & 3) * GCHUNK;
    const float* Xn = X + (size_t)n * (CC * HWP) + pbase;

    const int r = tid >> 1, q = tid & 1;
    const float* gsrc = Xn + (size_t)r * HWP + q * 8;
    if (tid < CC) chs[tid] = 0.f;

    float acc[16][4];
#pragma unroll
    for (int j = 0; j < 16; ++j)
#pragma unroll
        for (int z = 0; z < 4; ++z) acc[j][z] = 0.f;
    float cs = 0.f;

    const unsigned a_off = (unsigned)((wid * 16 + (lane & 15)) * PITCHB + (lane >> 4) * 16);
    const unsigned b_row = (unsigned)((lane >> 4) * 8 + (lane & 7));
    const unsigned b_koff = (unsigned)(((lane >> 3) & 1) * 16);
    const unsigned st_off = (unsigned)(r * PITCHB + q * 16);

    // prefetch distance 2: two register sets
    float4 pA0 = *(const float4*)(gsrc);
    float4 pA1 = *(const float4*)(gsrc + 4);
    float4 pB0 = *(const float4*)(gsrc + 16);
    float4 pB1 = *(const float4*)(gsrc + 16 + 4);

    for (int t = 0; t < 49; ++t) {
        char* base = sm + (t & 1) * GBUF;
        float4 v0 = (t & 1) ? pB0 : pA0;
        float4 v1 = (t & 1) ? pB1 : pA1;
        {
            unsigned h0 = pkbf(v0.x, v0.y), h1 = pkbf(v0.z, v0.w);
            unsigned h2 = pkbf(v1.x, v1.y), h3 = pkbf(v1.z, v1.w);
            *(uint4*)(base + st_off) = make_uint4(h0, h1, h2, h3);
            cs += ((v0.x + v0.y) + (v0.z + v0.w)) + ((v1.x + v1.y) + (v1.z + v1.w));
        }
        __syncthreads();
        if (t + 2 < 49) {   // issue load for tile t+2 into the set just consumed
            if (t & 1) {
                pB0 = *(const float4*)(gsrc + (t + 2) * 16);
                pB1 = *(const float4*)(gsrc + (t + 2) * 16 + 4);
            } else {
                pA0 = *(const float4*)(gsrc + (t + 2) * 16);
                pA1 = *(const float4*)(gsrc + (t + 2) * 16 + 4);
            }
        }
        const unsigned tb = smb + (unsigned)((t & 1) * GBUF);
        unsigned ah0, ah1, ah2, ah3;
        ldsm_x4(ah0, ah1, ah2, ah3, tb + a_off);
#pragma unroll
        for (int p = 0; p < 8; ++p) {
            const unsigned ba = tb + (unsigned)((16 * p + b_row) * PITCHB) + b_koff;
            unsigned bh0, bh1, bh2, bh3;
            ldsm_x4(bh0, bh1, bh2, bh3, ba);
            mma_bf16(acc[2*p],   ah0, ah1, ah2, ah3, bh0, bh1);
            mma_bf16(acc[2*p+1], ah0, ah1, ah2, ah3, bh2, bh3);
        }
    }

    __syncthreads();
    atomicAdd(&chs[r], cs);
    __syncthreads();
    if (tid < CC) d_cpart[blockIdx.x * CC + tid] = chs[tid];

    float* gp = d_gpart + (size_t)blockIdx.x * (CC * CC);
    const int row0 = wid * 16 + (lane >> 2);
#pragma unroll
    for (int j = 0; j < 16; ++j) {
        const int col = j * 8 + (lane & 3) * 2;
        *(float2*)(gp + row0 * CC + col)       = make_float2(acc[j][0], acc[j][1]);
        *(float2*)(gp + (row0 + 8) * CC + col) = make_float2(acc[j][2], acc[j][3]);
    }
}

// ---------------- kernel 2: reduce + zero barrier/trace ----------------
__global__ void reduce_kernel() {
    const int bid = blockIdx.x, tid = threadIdx.x;
    if (bid < 64) {
        const int i = bid * 256 + tid;
        float s = 0.f;
#pragma unroll 8
        for (int b = 0; b < GBLK; b++) s += d_gpart[(size_t)b * (CC * CC) + i];
        d_gram[i] = s;
    } else {
        if (tid < CC) {
            float s = 0.f;
#pragma unroll 8
            for (int b = 0; b < GBLK; b++) s += d_cpart[b * CC + tid];
            d_chsum[tid] = s;
        }
        if (tid == 128) { d_trace = 0.f; g_bar = 0u; }
    }
}

// ---------------- kernel 3: Newton-Schulz (R10 measured-best) ----------------
__device__ __forceinline__ void gsync(unsigned &tgt) {
    __threadfence();
    __syncthreads();
    tgt += NSB;
    if (threadIdx.x == 0) {
        atomicAdd(&g_bar, 1u);
        while (*(volatile unsigned*)&g_bar < tgt) {}
    }
    __syncthreads();
}
__device__ __forceinline__ float halfdot(const float* __restrict__ v,
                                         const float* __restrict__ M, int j) {
    float a0 = 0.f, a1 = 0.f, a2 = 0.f, a3 = 0.f;
#pragma unroll
    for (int k = 0; k < 64; k += 4) {
        float4 pv = *(const float4*)(v + k);
        a0 = fmaf(pv.x, __ldcg(&M[(k + 0) * CC + j]), a0);
        a1 = fmaf(pv.y, __ldcg(&M[(k + 1) * CC + j]), a1);
        a2 = fmaf(pv.z, __ldcg(&M[(k + 2) * CC + j]), a2);
        a3 = fmaf(pv.w, __ldcg(&M[(k + 3) * CC + j]), a3);
    }
    return (a0 + a1) + (a2 + a3);
}
__global__ void __launch_bounds__(256, 1) ns_kernel(const float* __restrict__ beta) {
    __shared__ float mean_s[CC], pr_s[CC], t1_s[CC], t2_s[CC];
    __shared__ float p1[2][CC], p2[2][CC], pu[2][CC];
    __shared__ float rtr_s;
    const int tid = threadIdx.x;
    const int j = tid & 127, h = tid >> 7;
    const int r = blockIdx.x;

    if (h == 0) mean_s[j] = d_chsum[j] * (1.f / (float)MTOT);
    __syncthreads();
    if (h == 0) {
        float sig = d_gram[r*CC + j] * (1.f / (float)MTOT) - mean_s[r] * mean_s[j]
                    + ((j == r) ? EPSI : 0.f);
        __stcg(&d_Sig[r*CC + j], sig);
        __stcg(&d_P2[0][r*CC + j], (j == r) ? 1.f : 0.f);
        if (j == r) atomicAdd(&d_trace, sig);
    }
    unsigned tgt = 0;
    gsync(tgt);
    if (tid == 0) rtr_s = 1.f / *(volatile float*)&d_trace;
    __syncthreads();
    const float rtr = rtr_s;

    int cur = 0;
    for (int it = 0; it < TITER; ++it) {
        const float* P = d_P2[cur];
        if (h == 0) pr_s[j] = __ldcg(&P[r*CC + j]);
        __syncthreads();
        p1[h][j] = halfdot(pr_s + h*64, P + (size_t)h*64*CC, j);
        __syncthreads();
        if (h == 0) t1_s[j] = p1[0][j] + p1[1][j];
        __syncthreads();
        p2[h][j] = halfdot(t1_s + h*64, P + (size_t)h*64*CC, j);
        __syncthreads();
        if (h == 0) t2_s[j] = p2[0][j] + p2[1][j];
        __syncthreads();
        pu[h][j] = halfdot(t2_s + h*64, d_Sig + (size_t)h*64*CC, j);
        __syncthreads();
        if (h == 0) {
            float u = pu[0][j] + pu[1][j];
            __stcg(&d_P2[1 - cur][r*CC + j], 1.5f * pr_s[j] - 0.5f * rtr * u);
        }
        gsync(tgt);
        cur ^= 1;
    }

    if (h == 0) {
        float w = __ldcg(&d_P2[cur][r*CC + j]) * sqrtf(rtr);
        d_wmf[r*CC + j] = w;
        t1_s[j] = w * mean_s[j];
    }
    __syncthreads();
    for (int s = 64; s > 0; s >>= 1) {
        if (tid < s) t1_s[tid] += t1_s[tid + s];
        __syncthreads();
    }
    if (tid == 0) d_bias2[r] = beta[r] - t1_s[0];
}

// ---------------- kernel 4: whitening, tf32 ldmatrix, warp tile m32 x n32 ----------
__global__ void __launch_bounds__(256) whit_kernel(const float* __restrict__ X,
                                                   float* __restrict__ Y) {
    extern __shared__ char sm[];
    const int tid = threadIdx.x, wid = tid >> 5, lane = tid & 31;
    const unsigned smb = smem_u32(sm);
    const int mw = wid & 3, pw = wid >> 2;   // m-group (32 rows), p-group (32 px)

    {   // stage wm -> tf32 smem [c][d] pitch WP
        const float4* wf = (const float4*)d_wmf;
        unsigned* wsm = (unsigned*)sm;
#pragma unroll 4
        for (int i = tid; i < 4096; i += 256) {
            int c = i >> 5, dg = (i & 31) * 4;
            float4 v = wf[i];
            *(uint4*)(wsm + c * WP + dg) =
                make_uint4(cvt_tf32(v.x), cvt_tf32(v.y), cvt_tf32(v.z), cvt_tf32(v.w));
        }
    }
    if (tid < 128) ((float*)(sm + S_BIAS))[tid] = d_bias2[tid];

    // ldmatrix lane addressing (bytes)
    unsigned a_base[2];
#pragma unroll
    for (int ma = 0; ma < 2; ++ma)
        a_base[ma] = smb
            + (unsigned)((mw * 32 + ma * 16 + (lane & 7) + ((lane >> 3) & 1) * 8) * WP * 4)
            + (unsigned)((lane >> 4) * 16);
    unsigned b_base[2];
#pragma unroll
    for (int qq = 0; qq < 2; ++qq)
        b_base[qq] = smb + S_X
            + (unsigned)((pw * 32 + qq * 16 + (lane & 7) + (lane >> 4) * 8) * XP2 * 4)
            + (unsigned)(((lane >> 3) & 1) * 16);

    const int cp = tid & 63;
    const int cd0 = (tid >> 6) * 32;
    unsigned* Xw = (unsigned*)(sm + S_X);

    float pf[32];
    {
        const int g0 = blockIdx.x * 4;
        const int n0 = g0 / 49, pp0 = (g0 % 49) * 64;
        const float* xp = X + ((size_t)n0 * CC + cd0) * HWP + pp0 + cp;
#pragma unroll
        for (int i = 0; i < 32; ++i) pf[i] = __ldg(xp + (size_t)i * HWP);
    }

    for (int t = 0; t < 4; ++t) {
        const int g = blockIdx.x * 4 + t;
        const int n = g / 49, p0 = (g % 49) * 64;
        if (t) __syncthreads();
        {
            unsigned* dst = Xw + cp * XP2 + cd0;
#pragma unroll
            for (int i = 0; i < 8; ++i)
                *(uint4*)(dst + 4 * i) = make_uint4(cvt_tf32(pf[4*i]), cvt_tf32(pf[4*i+1]),
                                                    cvt_tf32(pf[4*i+2]), cvt_tf32(pf[4*i+3]));
        }
        __syncthreads();

        if (t < 3) {
            const int g2 = blockIdx.x * 4 + t + 1;
            const int n2 = g2 / 49, pp2 = (g2 % 49) * 64;
            const float* xp = X + ((size_t)n2 * CC + cd0) * HWP + pp2 + cp;
#pragma unroll
            for (int i = 0; i < 32; ++i) pf[i] = __ldg(xp + (size_t)i * HWP);
        }

        float acc[2][4][4];
#pragma unroll
        for (int ma = 0; ma < 2; ++ma)
#pragma unroll
            for (int nb = 0; nb < 4; ++nb)
#pragma unroll
                for (int z = 0; z < 4; ++z) acc[ma][nb][z] = 0.f;

#pragma unroll
        for (int kt = 0; kt < 16; ++kt) {
            const unsigned ko = (unsigned)(kt * 32);
            unsigned a[2][4], b[2][4];
#pragma unroll
            for (int ma = 0; ma < 2; ++ma)
                ldsm_x4(a[ma][0], a[ma][1], a[ma][2], a[ma][3], a_base[ma] + ko);
#pragma unroll
            for (int qq = 0; qq < 2; ++qq)
                ldsm_x4(b[qq][0], b[qq][1], b[qq][2], b[qq][3], b_base[qq] + ko);
#pragma unroll
            for (int ma = 0; ma < 2; ++ma) {
                mma_tf32(acc[ma][0], a[ma][0], a[ma][1], a[ma][2], a[ma][3], b[0][0], b[0][1]);
                mma_tf32(acc[ma][1], a[ma][0], a[ma][1], a[ma][2], a[ma][3], b[0][2], b[0][3]);
                mma_tf32(acc[ma][2], a[ma][0], a[ma][1], a[ma][2], a[ma][3], b[1][0], b[1][1]);
                mma_tf32(acc[ma][3], a[ma][0], a[ma][1], a[ma][2], a[ma][3], b[1][2], b[1][3]);
            }
        }

#pragma unroll
        for (int ma = 0; ma < 2; ++ma) {
            const int row0 = mw * 32 + ma * 16 + (lane >> 2);
            const float b0 = ((const float*)(sm + S_BIAS))[row0];
            const float b1 = ((const float*)(sm + S_BIAS))[row0 + 8];
            float* y0 = Y + ((size_t)n * CC + row0) * HWP + p0 + pw * 32 + (lane & 3) * 2;
#pragma unroll
            for (int nb = 0; nb < 4; ++nb) {
                *(float2*)(y0 + 8 * nb)           = make_float2(acc[ma][nb][0] + b0, acc[ma][nb][1] + b0);
                *(float2*)(y0 + 8 * nb + 8 * HWP) = make_float2(acc[ma][nb][2] + b1, acc[ma][nb][3] + b1);
            }
        }
    }
}

// ---------------- launch ----------------
extern "C" void kernel_launch(void* const* d_in, const int* in_sizes, int n_in,
                              void* d_out, int out_size) {
    const float* X = (const float*)d_in[0];
    const float* beta = (const float*)d_in[1];
    float* Y = (float*)d_out;
    cudaFuncSetAttribute(whit_kernel, cudaFuncAttributeMaxDynamicSharedMemorySize, WHIT_SMEM);
    gram_kernel<<<GBLK, 256>>>(X);
    reduce_kernel<<<65, 256>>>();
    ns_kernel<<<NSB, 256>>>(beta);
    whit_kernel<<<784, 256, WHIT_SMEM>>>(X, Y);
}

// round 16
// speedup vs baseline: 1.3414x; 1.3414x over previous
#include <cuda_runtime.h>
#include <cuda_bf16.h>

#define NN    64
#define CC    128
#define HWP   3136
#define MTOT  200704
#define EPSI  1e-5f
#define TITER 10
#define NSB   128
#define GCHUNK 784
#define GBLK  256

// gram smem: [buf 0/1][128 rows][48B] (hi only, 1-pass)
#define PITCHB 48
#define GBUF   (128 * PITCHB)

// whit smem: wm [c=128][d, pitch 132 fl] tf32 ; X [p=64][d, pitch 132 fl] tf32
#define WP 132
#define XP2 132
#define S_X    (128 * WP * 4)
#define S_BIAS (S_X + 64 * XP2 * 4)
#define WHIT_SMEM (S_BIAS + 512)

// ---------------- scratch ----------------
__device__ float d_gpart[GBLK * CC * CC];
__device__ float d_cpart[GBLK * CC];
__device__ float d_gram[CC * CC];
__device__ float d_chsum[CC];
__device__ float d_Sig[CC * CC];
__device__ float d_P2[2][CC * CC];
__device__ float d_wmf[CC * CC];
__device__ float d_bias2[CC];
__device__ float d_trace;
__device__ unsigned g_bar;

// ---------------- helpers ----------------
__device__ __forceinline__ unsigned smem_u32(const void* p) {
    unsigned r; asm("{ .reg .u64 t; cvta.to.shared.u64 t, %1; cvt.u32.u64 %0, t; }" : "=r"(r) : "l"(p)); return r;
}
__device__ __forceinline__ void ldsm_x4(unsigned &r0, unsigned &r1, unsigned &r2, unsigned &r3, unsigned a) {
    asm volatile("ldmatrix.sync.aligned.m8n8.x4.shared.b16 {%0,%1,%2,%3}, [%4];"
                 : "=r"(r0), "=r"(r1), "=r"(r2), "=r"(r3) : "r"(a));
}
__device__ __forceinline__ void mma_bf16(float* d, unsigned a0, unsigned a1, unsigned a2, unsigned a3,
                                         unsigned b0, unsigned b1) {
    asm volatile("mma.sync.aligned.m16n8k16.row.col.f32.bf16.bf16.f32 "
                 "{%0,%1,%2,%3}, {%4,%5,%6,%7}, {%8,%9}, {%0,%1,%2,%3};"
                 : "+f"(d[0]), "+f"(d[1]), "+f"(d[2]), "+f"(d[3])
                 : "r"(a0), "r"(a1), "r"(a2), "r"(a3), "r"(b0), "r"(b1));
}
__device__ __forceinline__ void mma_tf32(float* d, unsigned a0, unsigned a1, unsigned a2, unsigned a3,
                                         unsigned b0, unsigned b1) {
    asm volatile("mma.sync.aligned.m16n8k8.row.col.f32.tf32.tf32.f32 "
                 "{%0,%1,%2,%3}, {%4,%5,%6,%7}, {%8,%9}, {%0,%1,%2,%3};"
                 : "+f"(d[0]), "+f"(d[1]), "+f"(d[2]), "+f"(d[3])
                 : "r"(a0), "r"(a1), "r"(a2), "r"(a3), "r"(b0), "r"(b1));
}
__device__ __forceinline__ unsigned pkbf(float a, float b) {
    __nv_bfloat162 t(__float2bfloat16(a), __float2bfloat16(b));
    return *(unsigned*)&t;
}
__device__ __forceinline__ unsigned cvt_tf32(float f) {
    unsigned r; asm("cvt.rna.tf32.f32 %0, %1;" : "=r"(r) : "f"(f)); return r;
}

// ---------------- kernel 1: Gram via mma.sync, 1-pass bf16 (R14 measured-good) ----
__global__ void __launch_bounds__(256, 2) gram_kernel(const float* __restrict__ X) {
    __shared__ __align__(16) char sm[2 * GBUF];
    __shared__ float chs[CC];
    const int tid = threadIdx.x, wid = tid >> 5, lane = tid & 31;
    const unsigned smb = smem_u32(sm);
    const int n = blockIdx.x >> 2;
    const int pbase = (blockIdx.x & 3) * GCHUNK;
    const float* Xn = X + (size_t)n * (CC * HWP) + pbase;

    const int r = tid >> 1, q = tid & 1;
    const float* gsrc = Xn + (size_t)r * HWP + q * 8;
    if (tid < CC) chs[tid] = 0.f;

    float acc[16][4];
#pragma unroll
    for (int j = 0; j < 16; ++j)
#pragma unroll
        for (int z = 0; z < 4; ++z) acc[j][z] = 0.f;
    float cs = 0.f;

    const unsigned a_off = (unsigned)((wid * 16 + (lane & 15)) * PITCHB + (lane >> 4) * 16);
    const unsigned b_row = (unsigned)((lane >> 4) * 8 + (lane & 7));
    const unsigned b_koff = (unsigned)(((lane >> 3) & 1) * 16);
    const unsigned st_off = (unsigned)(r * PITCHB + q * 16);

    float4 pv0 = *(const float4*)(gsrc);
    float4 pv1 = *(const float4*)(gsrc + 4);

    for (int t = 0; t < 49; ++t) {
        char* base = sm + (t & 1) * GBUF;
        {
            unsigned h0 = pkbf(pv0.x, pv0.y), h1 = pkbf(pv0.z, pv0.w);
            unsigned h2 = pkbf(pv1.x, pv1.y), h3 = pkbf(pv1.z, pv1.w);
            *(uint4*)(base + st_off) = make_uint4(h0, h1, h2, h3);
            cs += ((pv0.x + pv0.y) + (pv0.z + pv0.w)) + ((pv1.x + pv1.y) + (pv1.z + pv1.w));
        }
        __syncthreads();
        if (t < 48) {
            pv0 = *(const float4*)(gsrc + (t + 1) * 16);
            pv1 = *(const float4*)(gsrc + (t + 1) * 16 + 4);
        }
        const unsigned tb = smb + (unsigned)((t & 1) * GBUF);
        unsigned ah0, ah1, ah2, ah3;
        ldsm_x4(ah0, ah1, ah2, ah3, tb + a_off);
#pragma unroll
        for (int p = 0; p < 8; ++p) {
            const unsigned ba = tb + (unsigned)((16 * p + b_row) * PITCHB) + b_koff;
            unsigned bh0, bh1, bh2, bh3;
            ldsm_x4(bh0, bh1, bh2, bh3, ba);
            mma_bf16(acc[2*p],   ah0, ah1, ah2, ah3, bh0, bh1);
            mma_bf16(acc[2*p+1], ah0, ah1, ah2, ah3, bh2, bh3);
        }
    }

    __syncthreads();
    atomicAdd(&chs[r], cs);
    __syncthreads();
    if (tid < CC) d_cpart[blockIdx.x * CC + tid] = chs[tid];

    float* gp = d_gpart + (size_t)blockIdx.x * (CC * CC);
    const int row0 = wid * 16 + (lane >> 2);
#pragma unroll
    for (int j = 0; j < 16; ++j) {
        const int col = j * 8 + (lane & 3) * 2;
        *(float2*)(gp + row0 * CC + col)       = make_float2(acc[j][0], acc[j][1]);
        *(float2*)(gp + (row0 + 8) * CC + col) = make_float2(acc[j][2], acc[j][3]);
    }
}

// ---------------- kernel 2: reduce + zero barrier/trace ----------------
__global__ void reduce_kernel() {
    const int bid = blockIdx.x, tid = threadIdx.x;
    if (bid < 64) {
        const int i = bid * 256 + tid;
        float s = 0.f;
#pragma unroll 8
        for (int b = 0; b < GBLK; b++) s += d_gpart[(size_t)b * (CC * CC) + i];
        d_gram[i] = s;
    } else {
        if (tid < CC) {
            float s = 0.f;
#pragma unroll 8
            for (int b = 0; b < GBLK; b++) s += d_cpart[b * CC + tid];
            d_chsum[tid] = s;
        }
        if (tid == 128) { d_trace = 0.f; g_bar = 0u; }
    }
}

// ---------------- kernel 3: Newton-Schulz (R10 measured-best) ----------------
__device__ __forceinline__ void gsync(unsigned &tgt) {
    __threadfence();
    __syncthreads();
    tgt += NSB;
    if (threadIdx.x == 0) {
        atomicAdd(&g_bar, 1u);
        while (*(volatile unsigned*)&g_bar < tgt) {}
    }
    __syncthreads();
}
__device__ __forceinline__ float halfdot(const float* __restrict__ v,
                                         const float* __restrict__ M, int j) {
    float a0 = 0.f, a1 = 0.f, a2 = 0.f, a3 = 0.f;
#pragma unroll
    for (int k = 0; k < 64; k += 4) {
        float4 pv = *(const float4*)(v + k);
        a0 = fmaf(pv.x, __ldcg(&M[(k + 0) * CC + j]), a0);
        a1 = fmaf(pv.y, __ldcg(&M[(k + 1) * CC + j]), a1);
        a2 = fmaf(pv.z, __ldcg(&M[(k + 2) * CC + j]), a2);
        a3 = fmaf(pv.w, __ldcg(&M[(k + 3) * CC + j]), a3);
    }
    return (a0 + a1) + (a2 + a3);
}
__global__ void __launch_bounds__(256, 1) ns_kernel(const float* __restrict__ beta) {
    __shared__ float mean_s[CC], pr_s[CC], t1_s[CC], t2_s[CC];
    __shared__ float p1[2][CC], p2[2][CC], pu[2][CC];
    __shared__ float rtr_s;
    const int tid = threadIdx.x;
    const int j = tid & 127, h = tid >> 7;
    const int r = blockIdx.x;

    if (h == 0) mean_s[j] = d_chsum[j] * (1.f / (float)MTOT);
    __syncthreads();
    if (h == 0) {
        float sig = d_gram[r*CC + j] * (1.f / (float)MTOT) - mean_s[r] * mean_s[j]
                    + ((j == r) ? EPSI : 0.f);
        __stcg(&d_Sig[r*CC + j], sig);
        __stcg(&d_P2[0][r*CC + j], (j == r) ? 1.f : 0.f);
        if (j == r) atomicAdd(&d_trace, sig);
    }
    unsigned tgt = 0;
    gsync(tgt);
    if (tid == 0) rtr_s = 1.f / *(volatile float*)&d_trace;
    __syncthreads();
    const float rtr = rtr_s;

    int cur = 0;
    for (int it = 0; it < TITER; ++it) {
        const float* P = d_P2[cur];
        if (h == 0) pr_s[j] = __ldcg(&P[r*CC + j]);
        __syncthreads();
        p1[h][j] = halfdot(pr_s + h*64, P + (size_t)h*64*CC, j);
        __syncthreads();
        if (h == 0) t1_s[j] = p1[0][j] + p1[1][j];
        __syncthreads();
        p2[h][j] = halfdot(t1_s + h*64, P + (size_t)h*64*CC, j);
        __syncthreads();
        if (h == 0) t2_s[j] = p2[0][j] + p2[1][j];
        __syncthreads();
        pu[h][j] = halfdot(t2_s + h*64, d_Sig + (size_t)h*64*CC, j);
        __syncthreads();
        if (h == 0) {
            float u = pu[0][j] + pu[1][j];
            __stcg(&d_P2[1 - cur][r*CC + j], 1.5f * pr_s[j] - 0.5f * rtr * u);
        }
        gsync(tgt);
        cur ^= 1;
    }

    if (h == 0) {
        float w = __ldcg(&d_P2[cur][r*CC + j]) * sqrtf(rtr);
        d_wmf[r*CC + j] = w;
        t1_s[j] = w * mean_s[j];
    }
    __syncthreads();
    for (int s = 64; s > 0; s >>= 1) {
        if (tid < s) t1_s[tid] += t1_s[tid + s];
        __syncthreads();
    }
    if (tid == 0) d_bias2[r] = beta[r] - t1_s[0];
}

// ---------------- kernel 4: whitening, tf32 ldmatrix (m16n64) + B-frag double buffer ----
__global__ void __launch_bounds__(256) whit_kernel(const float* __restrict__ X,
                                                   float* __restrict__ Y) {
    extern __shared__ char sm[];
    const int tid = threadIdx.x, wid = tid >> 5, lane = tid & 31;
    const unsigned smb = smem_u32(sm);

    {   // stage wm -> tf32 smem [c][d] pitch WP, once per CTA
        const float4* wf = (const float4*)d_wmf;
        unsigned* wsm = (unsigned*)sm;
#pragma unroll 4
        for (int i = tid; i < 4096; i += 256) {
            int c = i >> 5, dg = (i & 31) * 4;
            float4 v = wf[i];
            *(uint4*)(wsm + c * WP + dg) =
                make_uint4(cvt_tf32(v.x), cvt_tf32(v.y), cvt_tf32(v.z), cvt_tf32(v.w));
        }
    }
    if (tid < 128) ((float*)(sm + S_BIAS))[tid] = d_bias2[tid];

    // ldmatrix lane addressing (bytes)
    const unsigned a_base = smb
        + (unsigned)((wid * 16 + (lane & 7) + ((lane >> 3) & 1) * 8) * WP * 4)
        + (unsigned)((lane >> 4) * 16);
    unsigned b_base[4];
#pragma unroll
    for (int qq = 0; qq < 4; ++qq)
        b_base[qq] = smb + S_X
            + (unsigned)((qq * 16 + (lane & 7) + (lane >> 4) * 8) * XP2 * 4)
            + (unsigned)(((lane >> 3) & 1) * 16);

    const int cp = tid & 63;
    const int cd0 = (tid >> 6) * 32;
    unsigned* Xw = (unsigned*)(sm + S_X);

    float pf[32];
    {
        const int g0 = blockIdx.x * 4;
        const int n0 = g0 / 49, pp0 = (g0 % 49) * 64;
        const float* xp = X + ((size_t)n0 * CC + cd0) * HWP + pp0 + cp;
#pragma unroll
        for (int i = 0; i < 32; ++i) pf[i] = __ldg(xp + (size_t)i * HWP);
    }

    for (int t = 0; t < 4; ++t) {
        const int g = blockIdx.x * 4 + t;
        const int n = g / 49, p0 = (g % 49) * 64;
        if (t) __syncthreads();
        {
            unsigned* dst = Xw + cp * XP2 + cd0;
#pragma unroll
            for (int i = 0; i < 8; ++i)
                *(uint4*)(dst + 4 * i) = make_uint4(cvt_tf32(pf[4*i]), cvt_tf32(pf[4*i+1]),
                                                    cvt_tf32(pf[4*i+2]), cvt_tf32(pf[4*i+3]));
        }
        __syncthreads();

        if (t < 3) {
            const int g2 = blockIdx.x * 4 + t + 1;
            const int n2 = g2 / 49, pp2 = (g2 % 49) * 64;
            const float* xp = X + ((size_t)n2 * CC + cd0) * HWP + pp2 + cp;
#pragma unroll
            for (int i = 0; i < 32; ++i) pf[i] = __ldg(xp + (size_t)i * HWP);
        }

        float acc[8][4];
#pragma unroll
        for (int jj = 0; jj < 8; ++jj)
#pragma unroll
            for (int z = 0; z < 4; ++z) acc[jj][z] = 0.f;

        // B-fragment double buffer: load kt+1's B while kt's MMAs issue
        unsigned bf[2][4][4];
#pragma unroll
        for (int qq = 0; qq < 4; ++qq)
            ldsm_x4(bf[0][qq][0], bf[0][qq][1], bf[0][qq][2], bf[0][qq][3], b_base[qq]);

#pragma unroll
        for (int kt = 0; kt < 16; ++kt) {
            const int cur = kt & 1, nxt = cur ^ 1;
            const unsigned ko = (unsigned)(kt * 32);
            unsigned a0, a1, a2, a3;
            ldsm_x4(a0, a1, a2, a3, a_base + ko);
            if (kt < 15) {
                const unsigned ko2 = (unsigned)((kt + 1) * 32);
#pragma unroll
                for (int qq = 0; qq < 4; ++qq)
                    ldsm_x4(bf[nxt][qq][0], bf[nxt][qq][1], bf[nxt][qq][2], bf[nxt][qq][3],
                            b_base[qq] + ko2);
            }
#pragma unroll
            for (int qq = 0; qq < 4; ++qq) {
                mma_tf32(acc[2*qq],   a0, a1, a2, a3, bf[cur][qq][0], bf[cur][qq][1]);
                mma_tf32(acc[2*qq+1], a0, a1, a2, a3, bf[cur][qq][2], bf[cur][qq][3]);
            }
        }

        const int row0 = wid * 16 + (lane >> 2);
        const float b0 = ((const float*)(sm + S_BIAS))[row0];
        const float b1 = ((const float*)(sm + S_BIAS))[row0 + 8];
        float* y0 = Y + ((size_t)n * CC + row0) * HWP + p0 + (lane & 3) * 2;
#pragma unroll
        for (int jj = 0; jj < 8; ++jj) {
            *(float2*)(y0 + 8 * jj)           = make_float2(acc[jj][0] + b0, acc[jj][1] + b0);
            *(float2*)(y0 + 8 * jj + 8 * HWP) = make_float2(acc[jj][2] + b1, acc[jj][3] + b1);
        }
    }
}

// ---------------- launch ----------------
extern "C" void kernel_launch(void* const* d_in, const int* in_sizes, int n_in,
                              void* d_out, int out_size) {
    const float* X = (const float*)d_in[0];
    const float* beta = (const float*)d_in[1];
    float* Y = (float*)d_out;
    cudaFuncSetAttribute(whit_kernel, cudaFuncAttributeMaxDynamicSharedMemorySize, WHIT_SMEM);
    gram_kernel<<<GBLK, 256>>>(X);
    reduce_kernel<<<65, 256>>>();
    ns_kernel<<<NSB, 256>>>(beta);
    whit_kernel<<<784, 256, WHIT_SMEM>>>(X, Y);
}

// round 17
// speedup vs baseline: 1.3531x; 1.0087x over previous
#include <cuda_runtime.h>
#include <cuda_bf16.h>

#define NN    64
#define CC    128
#define HWP   3136
#define MTOT  200704
#define EPSI  1e-5f
#define TITER 10
#define NSB   128
#define GCHUNK 784
#define GBLK  256

// gram smem: [buf 0/1][128 rows][48B] (hi only, 1-pass)
#define PITCHB 48
#define GBUF   (128 * PITCHB)

// whit smem: wm [c=128][d, pitch 132 fl] tf32 ; X [p=64][d, pitch 132 fl] tf32
#define WP 132
#define XP2 132
#define S_X    (128 * WP * 4)
#define S_BIAS (S_X + 64 * XP2 * 4)
#define WHIT_SMEM (S_BIAS + 512)

// ---------------- scratch ----------------
__device__ float d_gpart[GBLK * CC * CC];
__device__ float d_cpart[GBLK * CC];
__device__ float d_gram[CC * CC];
__device__ float d_chsum[CC];
__device__ float d_Sig[CC * CC];
__device__ float d_P2[2][CC * CC];
__device__ float d_wmf[CC * CC];
__device__ float d_bias2[CC];
__device__ float d_trace;
__device__ unsigned g_bars[512];   // 8 stripes, 256B apart (distinct LTS slices)

// ---------------- helpers ----------------
__device__ __forceinline__ unsigned smem_u32(const void* p) {
    unsigned r; asm("{ .reg .u64 t; cvta.to.shared.u64 t, %1; cvt.u32.u64 %0, t; }" : "=r"(r) : "l"(p)); return r;
}
__device__ __forceinline__ void ldsm_x4(unsigned &r0, unsigned &r1, unsigned &r2, unsigned &r3, unsigned a) {
    asm volatile("ldmatrix.sync.aligned.m8n8.x4.shared.b16 {%0,%1,%2,%3}, [%4];"
                 : "=r"(r0), "=r"(r1), "=r"(r2), "=r"(r3) : "r"(a));
}
__device__ __forceinline__ void mma_bf16(float* d, unsigned a0, unsigned a1, unsigned a2, unsigned a3,
                                         unsigned b0, unsigned b1) {
    asm volatile("mma.sync.aligned.m16n8k16.row.col.f32.bf16.bf16.f32 "
                 "{%0,%1,%2,%3}, {%4,%5,%6,%7}, {%8,%9}, {%0,%1,%2,%3};"
                 : "+f"(d[0]), "+f"(d[1]), "+f"(d[2]), "+f"(d[3])
                 : "r"(a0), "r"(a1), "r"(a2), "r"(a3), "r"(b0), "r"(b1));
}
__device__ __forceinline__ void mma_tf32(float* d, unsigned a0, unsigned a1, unsigned a2, unsigned a3,
                                         unsigned b0, unsigned b1) {
    asm volatile("mma.sync.aligned.m16n8k8.row.col.f32.tf32.tf32.f32 "
                 "{%0,%1,%2,%3}, {%4,%5,%6,%7}, {%8,%9}, {%0,%1,%2,%3};"
                 : "+f"(d[0]), "+f"(d[1]), "+f"(d[2]), "+f"(d[3])
                 : "r"(a0), "r"(a1), "r"(a2), "r"(a3), "r"(b0), "r"(b1));
}
__device__ __forceinline__ unsigned pkbf(float a, float b) {
    __nv_bfloat162 t(__float2bfloat16(a), __float2bfloat16(b));
    return *(unsigned*)&t;
}
__device__ __forceinline__ unsigned cvt_tf32(float f) {
    unsigned r; asm("cvt.rna.tf32.f32 %0, %1;" : "=r"(r) : "f"(f)); return r;
}

// ---------------- kernel 1: Gram via mma.sync, 1-pass bf16 (measured-good) ----
__global__ void __launch_bounds__(256, 2) gram_kernel(const float* __restrict__ X) {
    __shared__ __align__(16) char sm[2 * GBUF];
    __shared__ float chs[CC];
    const int tid = threadIdx.x, wid = tid >> 5, lane = tid & 31;
    const unsigned smb = smem_u32(sm);
    const int n = blockIdx.x >> 2;
    const int pbase = (blockIdx.x & 3) * GCHUNK;
    const float* Xn = X + (size_t)n * (CC * HWP) + pbase;

    const int r = tid >> 1, q = tid & 1;
    const float* gsrc = Xn + (size_t)r * HWP + q * 8;
    if (tid < CC) chs[tid] = 0.f;

    float acc[16][4];
#pragma unroll
    for (int j = 0; j < 16; ++j)
#pragma unroll
        for (int z = 0; z < 4; ++z) acc[j][z] = 0.f;
    float cs = 0.f;

    const unsigned a_off = (unsigned)((wid * 16 + (lane & 15)) * PITCHB + (lane >> 4) * 16);
    const unsigned b_row = (unsigned)((lane >> 4) * 8 + (lane & 7));
    const unsigned b_koff = (unsigned)(((lane >> 3) & 1) * 16);
    const unsigned st_off = (unsigned)(r * PITCHB + q * 16);

    float4 pv0 = *(const float4*)(gsrc);
    float4 pv1 = *(const float4*)(gsrc + 4);

    for (int t = 0; t < 49; ++t) {
        char* base = sm + (t & 1) * GBUF;
        {
            unsigned h0 = pkbf(pv0.x, pv0.y), h1 = pkbf(pv0.z, pv0.w);
            unsigned h2 = pkbf(pv1.x, pv1.y), h3 = pkbf(pv1.z, pv1.w);
            *(uint4*)(base + st_off) = make_uint4(h0, h1, h2, h3);
            cs += ((pv0.x + pv0.y) + (pv0.z + pv0.w)) + ((pv1.x + pv1.y) + (pv1.z + pv1.w));
        }
        __syncthreads();
        if (t < 48) {
            pv0 = *(const float4*)(gsrc + (t + 1) * 16);
            pv1 = *(const float4*)(gsrc + (t + 1) * 16 + 4);
        }
        const unsigned tb = smb + (unsigned)((t & 1) * GBUF);
        unsigned ah0, ah1, ah2, ah3;
        ldsm_x4(ah0, ah1, ah2, ah3, tb + a_off);
#pragma unroll
        for (int p = 0; p < 8; ++p) {
            const unsigned ba = tb + (unsigned)((16 * p + b_row) * PITCHB) + b_koff;
            unsigned bh0, bh1, bh2, bh3;
            ldsm_x4(bh0, bh1, bh2, bh3, ba);
            mma_bf16(acc[2*p],   ah0, ah1, ah2, ah3, bh0, bh1);
            mma_bf16(acc[2*p+1], ah0, ah1, ah2, ah3, bh2, bh3);
        }
    }

    __syncthreads();
    atomicAdd(&chs[r], cs);
    __syncthreads();
    if (tid < CC) d_cpart[blockIdx.x * CC + tid] = chs[tid];

    float* gp = d_gpart + (size_t)blockIdx.x * (CC * CC);
    const int row0 = wid * 16 + (lane >> 2);
#pragma unroll
    for (int j = 0; j < 16; ++j) {
        const int col = j * 8 + (lane & 3) * 2;
        *(float2*)(gp + row0 * CC + col)       = make_float2(acc[j][0], acc[j][1]);
        *(float2*)(gp + (row0 + 8) * CC + col) = make_float2(acc[j][2], acc[j][3]);
    }
}

// ---------------- kernel 2: reduce + zero barriers/trace ----------------
__global__ void reduce_kernel() {
    const int bid = blockIdx.x, tid = threadIdx.x;
    if (bid < 64) {
        const int i = bid * 256 + tid;
        float s = 0.f;
#pragma unroll 8
        for (int b = 0; b < GBLK; b++) s += d_gpart[(size_t)b * (CC * CC) + i];
        d_gram[i] = s;
    } else {
        if (tid < CC) {
            float s = 0.f;
#pragma unroll 8
            for (int b = 0; b < GBLK; b++) s += d_cpart[b * CC + tid];
            d_chsum[tid] = s;
        }
        if (tid == 128) d_trace = 0.f;
        if (tid >= 136 && tid < 144) g_bars[(tid - 136) * 64] = 0u;
    }
}

// ---------------- kernel 3: Newton-Schulz, striped grid barrier ----------------
__device__ __forceinline__ void gsync(unsigned &tgt) {
    __threadfence();
    __syncthreads();
    tgt += NSB;
    if (threadIdx.x == 0) {
        atomicAdd(&g_bars[(blockIdx.x & 7) * 64], 1u);
        unsigned s;
        do {
            s = 0;
#pragma unroll
            for (int i = 0; i < 8; ++i) s += *(volatile unsigned*)&g_bars[i * 64];
        } while (s < tgt);
    }
    __syncthreads();
}
__device__ __forceinline__ float halfdot(const float* __restrict__ v,
                                         const float* __restrict__ M, int j) {
    float a0 = 0.f, a1 = 0.f, a2 = 0.f, a3 = 0.f;
#pragma unroll
    for (int k = 0; k < 64; k += 4) {
        float4 pv = *(const float4*)(v + k);
        a0 = fmaf(pv.x, __ldcg(&M[(k + 0) * CC + j]), a0);
        a1 = fmaf(pv.y, __ldcg(&M[(k + 1) * CC + j]), a1);
        a2 = fmaf(pv.z, __ldcg(&M[(k + 2) * CC + j]), a2);
        a3 = fmaf(pv.w, __ldcg(&M[(k + 3) * CC + j]), a3);
    }
    return (a0 + a1) + (a2 + a3);
}
__global__ void __launch_bounds__(256, 1) ns_kernel(const float* __restrict__ beta) {
    __shared__ float mean_s[CC], pr_s[CC], t1_s[CC], t2_s[CC];
    __shared__ float p1[2][CC], p2[2][CC], pu[2][CC];
    __shared__ float rtr_s;
    const int tid = threadIdx.x;
    const int j = tid & 127, h = tid >> 7;
    const int r = blockIdx.x;

    if (h == 0) mean_s[j] = d_chsum[j] * (1.f / (float)MTOT);
    __syncthreads();
    if (h == 0) {
        float sig = d_gram[r*CC + j] * (1.f / (float)MTOT) - mean_s[r] * mean_s[j]
                    + ((j == r) ? EPSI : 0.f);
        __stcg(&d_Sig[r*CC + j], sig);
        __stcg(&d_P2[0][r*CC + j], (j == r) ? 1.f : 0.f);
        if (j == r) atomicAdd(&d_trace, sig);
    }
    unsigned tgt = 0;
    gsync(tgt);
    if (tid == 0) rtr_s = 1.f / *(volatile float*)&d_trace;
    __syncthreads();
    const float rtr = rtr_s;

    int cur = 0;
    for (int it = 0; it < TITER; ++it) {
        const float* P = d_P2[cur];
        if (h == 0) pr_s[j] = __ldcg(&P[r*CC + j]);
        __syncthreads();
        p1[h][j] = halfdot(pr_s + h*64, P + (size_t)h*64*CC, j);
        __syncthreads();
        if (h == 0) t1_s[j] = p1[0][j] + p1[1][j];
        __syncthreads();
        p2[h][j] = halfdot(t1_s + h*64, P + (size_t)h*64*CC, j);
        __syncthreads();
        if (h == 0) t2_s[j] = p2[0][j] + p2[1][j];
        __syncthreads();
        pu[h][j] = halfdot(t2_s + h*64, d_Sig + (size_t)h*64*CC, j);
        __syncthreads();
        if (h == 0) {
            float u = pu[0][j] + pu[1][j];
            __stcg(&d_P2[1 - cur][r*CC + j], 1.5f * pr_s[j] - 0.5f * rtr * u);
        }
        gsync(tgt);
        cur ^= 1;
    }

    if (h == 0) {
        float w = __ldcg(&d_P2[cur][r*CC + j]) * sqrtf(rtr);
        d_wmf[r*CC + j] = w;
        t1_s[j] = w * mean_s[j];
    }
    __syncthreads();
    for (int s = 64; s > 0; s >>= 1) {
        if (tid < s) t1_s[tid] += t1_s[tid + s];
        __syncthreads();
    }
    if (tid == 0) d_bias2[r] = beta[r] - t1_s[0];
}

// ---------------- kernel 4: whitening, tf32 ldmatrix (R14 measured-good) ----------
__global__ void __launch_bounds__(256) whit_kernel(const float* __restrict__ X,
                                                   float* __restrict__ Y) {
    extern __shared__ char sm[];
    const int tid = threadIdx.x, wid = tid >> 5, lane = tid & 31;
    const unsigned smb = smem_u32(sm);

    {   // stage wm -> tf32 smem [c][d] pitch WP, once per CTA
        const float4* wf = (const float4*)d_wmf;
        unsigned* wsm = (unsigned*)sm;
#pragma unroll 4
        for (int i = tid; i < 4096; i += 256) {
            int c = i >> 5, dg = (i & 31) * 4;
            float4 v = wf[i];
            *(uint4*)(wsm + c * WP + dg) =
                make_uint4(cvt_tf32(v.x), cvt_tf32(v.y), cvt_tf32(v.z), cvt_tf32(v.w));
        }
    }
    if (tid < 128) ((float*)(sm + S_BIAS))[tid] = d_bias2[tid];

    const unsigned a_base = smb
        + (unsigned)((wid * 16 + (lane & 7) + ((lane >> 3) & 1) * 8) * WP * 4)
        + (unsigned)((lane >> 4) * 16);
    unsigned b_base[4];
#pragma unroll
    for (int qq = 0; qq < 4; ++qq)
        b_base[qq] = smb + S_X
            + (unsigned)((qq * 16 + (lane & 7) + (lane >> 4) * 8) * XP2 * 4)
            + (unsigned)(((lane >> 3) & 1) * 16);

    const int cp = tid & 63;
    const int cd0 = (tid >> 6) * 32;
    unsigned* Xw = (unsigned*)(sm + S_X);

    float pf[32];
    {
        const int g0 = blockIdx.x * 4;
        const int n0 = g0 / 49, pp0 = (g0 % 49) * 64;
        const float* xp = X + ((size_t)n0 * CC + cd0) * HWP + pp0 + cp;
#pragma unroll
        for (int i = 0; i < 32; ++i) pf[i] = __ldg(xp + (size_t)i * HWP);
    }

    for (int t = 0; t < 4; ++t) {
        const int g = blockIdx.x * 4 + t;
        const int n = g / 49, p0 = (g % 49) * 64;
        if (t) __syncthreads();
        {
            unsigned* dst = Xw + cp * XP2 + cd0;
#pragma unroll
            for (int i = 0; i < 8; ++i)
                *(uint4*)(dst + 4 * i) = make_uint4(cvt_tf32(pf[4*i]), cvt_tf32(pf[4*i+1]),
                                                    cvt_tf32(pf[4*i+2]), cvt_tf32(pf[4*i+3]));
        }
        __syncthreads();

        if (t < 3) {
            const int g2 = blockIdx.x * 4 + t + 1;
            const int n2 = g2 / 49, pp2 = (g2 % 49) * 64;
            const float* xp = X + ((size_t)n2 * CC + cd0) * HWP + pp2 + cp;
#pragma unroll
            for (int i = 0; i < 32; ++i) pf[i] = __ldg(xp + (size_t)i * HWP);
        }

        float acc[8][4];
#pragma unroll
        for (int jj = 0; jj < 8; ++jj)
#pragma unroll
            for (int z = 0; z < 4; ++z) acc[jj][z] = 0.f;

#pragma unroll
        for (int kt = 0; kt < 16; ++kt) {
            const unsigned ko = (unsigned)(kt * 32);
            unsigned a0, a1, a2, a3;
            ldsm_x4(a0, a1, a2, a3, a_base + ko);
#pragma unroll
            for (int qq = 0; qq < 4; ++qq) {
                unsigned b0, b1, b2, b3;
                ldsm_x4(b0, b1, b2, b3, b_base[qq] + ko);
                mma_tf32(acc[2*qq],   a0, a1, a2, a3, b0, b1);
                mma_tf32(acc[2*qq+1], a0, a1, a2, a3, b2, b3);
            }
        }

        const int row0 = wid * 16 + (lane >> 2);
        const float b0 = ((const float*)(sm + S_BIAS))[row0];
        const float b1 = ((const float*)(sm + S_BIAS))[row0 + 8];
        float* y0 = Y + ((size_t)n * CC + row0) * HWP + p0 + (lane & 3) * 2;
#pragma unroll
        for (int jj = 0; jj < 8; ++jj) {
            *(float2*)(y0 + 8 * jj)           = make_float2(acc[jj][0] + b0, acc[jj][1] + b0);
            *(float2*)(y0 + 8 * jj + 8 * HWP) = make_float2(acc[jj][2] + b1, acc[jj][3] + b1);
        }
    }
}

// ---------------- launch ----------------
extern "C" void kernel_launch(void* const* d_in, const int* in_sizes, int n_in,
                              void* d_out, int out_size) {
    const float* X = (const float*)d_in[0];
    const float* beta = (const float*)d_in[1];
    float* Y = (float*)d_out;
    cudaFuncSetAttribute(whit_kernel, cudaFuncAttributeMaxDynamicSharedMemorySize, WHIT_SMEM);
    gram_kernel<<<GBLK, 256>>>(X);
    reduce_kernel<<<65, 256>>>();
    ns_kernel<<<NSB, 256>>>(beta);
    whit_kernel<<<784, 256, WHIT_SMEM>>>(X, Y);
}